// round 10
// baseline (speedup 1.0000x reference)
#include <cuda_runtime.h>
#include <cuda_fp16.h>
#include <cstdint>

#define Hdim 128
#define HALF 64
#define NMAX 200000
#define EMAX 400000
#define T 128
#define SAc 200             // cell A stride (fp16): 400B ≡ 16 mod 128 → conflict-free ldsm
#define SAe 264             // edge A stride: 528B ≡ 16 mod 128
#define SB 72               // B stride: 144B ≡ 16 mod 128
// cell smem: A(64x200) 0..25600, B0 25600, B1 44032, red 62464..63488
#define C_B0 25600
#define C_B1 44032
#define C_RED 62464
#define SMEM_CELL 63488
// edge smem: A(64x264) 0..33792, B0 33792, B1 52224, red 70656..71680
#define E_B0 33792
#define E_B1 52224
#define E_RED 70656
#define SMEM_EDGE 71680

// ---------------- static device scratch ----------------
__device__ float  g_agg[(size_t)NMAX * HALF];
__device__ __half g_aggh[(size_t)NMAX * HALF];
__device__ __half g_xh[(size_t)NMAX * Hdim];
__device__ __half g_xc2h[(size_t)NMAX * Hdim];
__device__ __half g_eah[(size_t)EMAX * Hdim];
// transposed fp16 weights [n=128][K]; cb1:0 cb2:24576 cb3:40960 eb1:57344 eb2:106496 eb3:122880
__device__ __half g_wt[139264];

// ---------------- helpers ----------------
__device__ __forceinline__ uint32_t smem_u32(const void* p) {
    uint32_t a;
    asm("{ .reg .u64 t; cvta.to.shared.u64 t, %1; cvt.u32.u64 %0, t; }" : "=r"(a) : "l"(p));
    return a;
}
__device__ __forceinline__ void ldsm4(uint32_t r[4], uint32_t a) {
    asm volatile("ldmatrix.sync.aligned.m8n8.x4.shared.b16 {%0,%1,%2,%3}, [%4];"
        : "=r"(r[0]), "=r"(r[1]), "=r"(r[2]), "=r"(r[3]) : "r"(a));
}
__device__ __forceinline__ void mma16(float d[4], const uint32_t a[4], uint32_t b0, uint32_t b1) {
    asm volatile("mma.sync.aligned.m16n8k16.row.col.f32.f16.f16.f32 "
        "{%0,%1,%2,%3}, {%4,%5,%6,%7}, {%8,%9}, {%0,%1,%2,%3};"
        : "+f"(d[0]), "+f"(d[1]), "+f"(d[2]), "+f"(d[3])
        : "r"(a[0]), "r"(a[1]), "r"(a[2]), "r"(a[3]), "r"(b0), "r"(b1));
}
__device__ __forceinline__ float silu_f(float v) { return v * (1.0f / (1.0f + __expf(-v))); }
#define CPA16(dst, src) asm volatile("cp.async.cg.shared.global [%0], [%1], 16;" :: "r"(dst), "l"(src) : "memory")
#define CPA_COMMIT() asm volatile("cp.async.commit_group;" ::: "memory")
#define CPA_W0() asm volatile("cp.async.wait_group 0;" ::: "memory")
#define CPA_W1() asm volatile("cp.async.wait_group 1;" ::: "memory")

// ---------------- small kernels ----------------
// zero agg + convert x -> fp16 in one launch
__global__ void k_init(const float* __restrict__ x, int N) {
    int i = blockIdx.x * blockDim.x + threadIdx.x;
    int nz = N * 16;                  // agg float4 count
    if (i < nz) ((float4*)g_agg)[i] = make_float4(0.f, 0.f, 0.f, 0.f);
    int nc = N * 32;                  // x float4 count
    if (i < nc) {
        float4 v = ((const float4*)x)[i];
        half2 h0 = __floats2half2_rn(v.x, v.y);
        half2 h1 = __floats2half2_rn(v.z, v.w);
        *(uint2*)(g_xh + (size_t)i * 4) = make_uint2(*(uint32_t*)&h0, *(uint32_t*)&h1);
    }
}
__global__ void k_cvt(const float* __restrict__ src, __half* __restrict__ dst, int n4) {
    int i = blockIdx.x * blockDim.x + threadIdx.x;
    if (i >= n4) return;
    float4 v = ((const float4*)src)[i];
    half2 h0 = __floats2half2_rn(v.x, v.y);
    half2 h1 = __floats2half2_rn(v.z, v.w);
    *(uint2*)(dst + (size_t)i * 4) = make_uint2(*(uint32_t*)&h0, *(uint32_t*)&h1);
}
__global__ void k_scatter(const float* __restrict__ ea, const int* __restrict__ ei, int E) {
    int gid = blockIdx.x * blockDim.x + threadIdx.x;
    int e = gid >> 5;
    if (e >= E) return;
    int c4 = (gid & 31) << 2;
    float4 v = *(const float4*)(ea + (size_t)e * Hdim + c4);
    half2 h0 = __floats2half2_rn(v.x, v.y);
    half2 h1 = __floats2half2_rn(v.z, v.w);
    *(uint2*)(g_eah + (size_t)e * Hdim + c4) = make_uint2(*(uint32_t*)&h0, *(uint32_t*)&h1);
    float* base;
    if (c4 < HALF) { int r = ei[E + e]; base = g_agg + (size_t)r * HALF + c4; }
    else           { int s = ei[e];     base = g_agg + (size_t)s * HALF + (c4 - HALF); }
    asm volatile("red.global.add.v4.f32 [%0], {%1,%2,%3,%4};"
        :: "l"(base), "f"(v.x), "f"(v.y), "f"(v.z), "f"(v.w) : "memory");
}
__global__ void k_prep_all(const float* cw1, const float* cw2, const float* cw3,
                           const float* ew1, const float* ew2, const float* ew3) {
    int idx = blockIdx.x * blockDim.x + threadIdx.x;
    if (idx >= 139264) return;
    const float* src; int K, off;
    if      (idx < 24576)  { src = cw1; K = 192; off = 0; }
    else if (idx < 40960)  { src = cw2; K = 128; off = 24576; }
    else if (idx < 57344)  { src = cw3; K = 128; off = 40960; }
    else if (idx < 106496) { src = ew1; K = 384; off = 57344; }
    else if (idx < 122880) { src = ew2; K = 128; off = 106496; }
    else                   { src = ew3; K = 128; off = 122880; }
    int l = idx - off;
    int n = l / K, k = l - n * K;
    g_wt[idx] = __float2half(src[k * Hdim + n]);
}

// ---------------- async staging (64-row tiles, 128 threads) ----------------
__device__ __forceinline__ void cpaH(const __half* __restrict__ src, int ld, int ncol8,
                                     int rowbase, int nrows, uint32_t dstbase, int strideH, int tid) {
    int tot = 64 * ncol8;
    for (int idx = tid; idx < tot; idx += T) {
        int r = idx / ncol8, c8 = (idx - r * ncol8) * 8;
        int grow = rowbase + r; if (grow >= nrows) grow = nrows - 1;
        CPA16(dstbase + (uint32_t)(r * strideH + c8) * 2, src + (size_t)grow * ld + c8);
    }
    CPA_COMMIT();
}
__device__ __forceinline__ void cpaGh(const __half* __restrict__ src, const int* __restrict__ eidx,
                                      int rowbase, uint32_t dstbase, int strideH, int tid) {
#pragma unroll
    for (int i = 0; i < 8; i++) {
        int idx = tid + i * T;
        int r = idx >> 4, c8 = (idx & 15) * 8;
        int srow = __ldg(eidx + rowbase + r);
        CPA16(dstbase + (uint32_t)(r * strideH + c8) * 2, src + (size_t)srow * Hdim + c8);
    }
    CPA_COMMIT();
}
__device__ __forceinline__ void cpaB(const __half* __restrict__ wt, int K, int k0,
                                     uint32_t dstbase, int tid) {
#pragma unroll
    for (int i = 0; i < 8; i++) {
        int idx = tid + i * T;
        int n = idx >> 3, c8 = (idx & 7) * 8;
        CPA16(dstbase + (uint32_t)(n * SB + c8) * 2, wt + (size_t)n * K + k0 + c8);
    }
    CPA_COMMIT();
}

// ---------------- MMA over one 64-col K chunk (warp: 32 rows x 64 cols) ----------------
__device__ __forceinline__ void mma_chunk(uint32_t aB, uint32_t bB, float acc[2][8][4], int saStrideB) {
#pragma unroll
    for (int ks = 0; ks < 4; ks++) {
        uint32_t A0[4], A1[4];
        ldsm4(A0, aB + ks * 32);
        ldsm4(A1, aB + ks * 32 + 16 * saStrideB);
#pragma unroll
        for (int q = 0; q < 4; q++) {
            uint32_t B[4];
            ldsm4(B, bB + ks * 32 + q * (16 * SB * 2));
            mma16(acc[0][2 * q],     A0, B[0], B[1]);
            mma16(acc[1][2 * q],     A1, B[0], B[1]);
            mma16(acc[0][2 * q + 1], A0, B[2], B[3]);
            mma16(acc[1][2 * q + 1], A1, B[2], B[3]);
        }
    }
}
__device__ __forceinline__ void zero_acc(float acc[2][8][4]) {
#pragma unroll
    for (int m = 0; m < 2; m++)
#pragma unroll
        for (int t = 0; t < 8; t++)
#pragma unroll
            for (int i = 0; i < 4; i++) acc[m][t][i] = 0.0f;
}

// ---------------- epilogues (4 warps: rg = w&1, cg = w>>1) ----------------
__device__ __forceinline__ void epi_act(float acc[2][8][4], const float* __restrict__ bias,
                                        char* smA, int strideH, int w, int lane) {
    int rg = w & 1, cg = w >> 1, c2 = (lane & 3) * 2, r0 = rg * 32 + (lane >> 2);
#pragma unroll
    for (int mt = 0; mt < 2; mt++)
#pragma unroll
        for (int nt = 0; nt < 8; nt++) {
            int col = cg * 64 + nt * 8 + c2;
            float2 b = __ldg((const float2*)(bias + col));
            int row = r0 + mt * 16;
            half2 h0 = __floats2half2_rn(silu_f(acc[mt][nt][0] + b.x), silu_f(acc[mt][nt][1] + b.y));
            *(half2*)(smA + ((size_t)(row * strideH + col)) * 2) = h0;
            half2 h1 = __floats2half2_rn(silu_f(acc[mt][nt][2] + b.x), silu_f(acc[mt][nt][3] + b.y));
            *(half2*)(smA + ((size_t)((row + 8) * strideH + col)) * 2) = h1;
        }
}
// LN: if smA != null -> write fp16 LN result to smem cols 0-127; else gmem outputs
__device__ __forceinline__ void epi_ln(float acc[2][8][4],
    const float* __restrict__ bias, const float* __restrict__ gam, const float* __restrict__ bet,
    float* s_red, int rowbase, int nrows, char* smA, int strideH,
    __half* out1h, const float* __restrict__ resid, float* out2, int w, int lane)
{
    int rg = w & 1, cg = w >> 1, c2 = (lane & 3) * 2;
    float vals[2][2][16];
#pragma unroll
    for (int mt = 0; mt < 2; mt++)
#pragma unroll
        for (int nt = 0; nt < 8; nt++) {
            int col = cg * 64 + nt * 8 + c2;
            float2 b = __ldg((const float2*)(bias + col));
            vals[mt][0][2 * nt]     = acc[mt][nt][0] + b.x;
            vals[mt][0][2 * nt + 1] = acc[mt][nt][1] + b.y;
            vals[mt][1][2 * nt]     = acc[mt][nt][2] + b.x;
            vals[mt][1][2 * nt + 1] = acc[mt][nt][3] + b.y;
        }
#pragma unroll
    for (int mt = 0; mt < 2; mt++)
#pragma unroll
        for (int h = 0; h < 2; h++) {
            float s = 0.0f, q = 0.0f;
#pragma unroll
            for (int j = 0; j < 16; j++) { float v = vals[mt][h][j]; s += v; q += v * v; }
            s += __shfl_xor_sync(0xffffffffu, s, 1);
            q += __shfl_xor_sync(0xffffffffu, q, 1);
            s += __shfl_xor_sync(0xffffffffu, s, 2);
            q += __shfl_xor_sync(0xffffffffu, q, 2);
            int r = rg * 32 + mt * 16 + h * 8 + (lane >> 2);
            if ((lane & 3) == 0) {
                s_red[cg * 64 + r] = s;
                s_red[128 + cg * 64 + r] = q;
            }
        }
    __syncthreads();
#pragma unroll
    for (int mt = 0; mt < 2; mt++)
#pragma unroll
        for (int h = 0; h < 2; h++) {
            int r = rg * 32 + mt * 16 + h * 8 + (lane >> 2);
            float st = s_red[r] + s_red[64 + r];
            float qt = s_red[128 + r] + s_red[192 + r];
            float mu = st * (1.0f / Hdim);
            float inv = rsqrtf(qt * (1.0f / Hdim) - mu * mu + 1e-5f);
            int grow = rowbase + r;
#pragma unroll
            for (int nt = 0; nt < 8; nt++) {
                int col = cg * 64 + nt * 8 + c2;
                float2 g = __ldg((const float2*)(gam + col));
                float2 b = __ldg((const float2*)(bet + col));
                float2 o;
                o.x = (vals[mt][h][2 * nt]     - mu) * inv * g.x + b.x;
                o.y = (vals[mt][h][2 * nt + 1] - mu) * inv * g.y + b.y;
                if (smA) {
                    *(half2*)(smA + ((size_t)(r * strideH + col)) * 2) = __floats2half2_rn(o.x, o.y);
                } else if (grow < nrows) {
                    size_t base = (size_t)grow * Hdim + col;
                    if (out1h) *(half2*)(out1h + base) = __floats2half2_rn(o.x, o.y);
                    if (out2) {
                        float2 rv = *(const float2*)(resid + base);
                        *(float2*)(out2 + base) = make_float2(o.x + rv.x, o.y + rv.y);
                    }
                }
            }
        }
}

// ---------------- fused CellBlock: both mp rounds, [x|agg](192)->128->128->LN, twice ----------------
__global__ void __launch_bounds__(T, 3) k_cell(
    const __half* __restrict__ xh, const __half* __restrict__ aggh,
    const __half* __restrict__ w1, const __half* __restrict__ w2, const __half* __restrict__ w3,
    const float* __restrict__ b1, const float* __restrict__ b2, const float* __restrict__ b3,
    const float* __restrict__ gam, const float* __restrict__ bet,
    const float* __restrict__ x32, float* __restrict__ out_x, __half* __restrict__ xc2h,
    int nrows)
{
    extern __shared__ char smc[];
    uint32_t sa = smem_u32(smc);
    uint32_t sbB[2] = { sa + C_B0, sa + C_B1 };
    float* s_red = (float*)(smc + C_RED);
    int tid = threadIdx.x, w = tid >> 5, lane = tid & 31;
    int rowbase = blockIdx.x * 64;
    int arow = (lane & 7) + ((lane >> 3) & 1) * 8;
    int acol = (lane >> 4) * 8;
    int b_r = (lane & 7) + (lane >> 4) * 8;
    int b_c = ((lane >> 3) & 1) * 8;
    int rg = w & 1;
    uint32_t aW = sa + (uint32_t)((rg * 32 + arow) * SAc + acol) * 2;
    uint32_t bo = (uint32_t)(((w >> 1) * 64 + b_r) * SB + b_c) * 2;
    float acc[2][8][4];

    // stage A: x -> cols 0-127, agg -> cols 128-191
    cpaH(xh, Hdim, 16, rowbase, nrows, sa, SAc, tid);
    cpaH(aggh, HALF, 8, rowbase, nrows, sa + 128u * 2, SAc, tid);
    cpaB(w1, 192, 0, sbB[0], tid);

    // ---- ROUND 1 ----  (chunk parity cc: 0..6)
    zero_acc(acc);
    for (int c = 0; c < 3; c++) {                       // cc 0,1,2 -> bufs 0,1,0
        CPA_W0(); __syncthreads();
        if (c < 2) cpaB(w1, 192, (c + 1) * 64, sbB[(c + 1) & 1], tid);
        mma_chunk(aW + (uint32_t)(c * 64) * 2, sbB[c & 1] + bo, acc, SAc * 2);
    }
    __syncthreads();
    cpaB(w2, 128, 0, sbB[1], tid);                      // cc3 -> buf1
    epi_act(acc, b1, smc, SAc, w, lane);                // act1 -> cols 0-127
    zero_acc(acc);
    for (int c = 0; c < 2; c++) {                       // cc 3,4 -> bufs 1,0
        CPA_W0(); __syncthreads();
        if (c < 1) cpaB(w2, 128, 64, sbB[0], tid);
        mma_chunk(aW + (uint32_t)(c * 64) * 2, sbB[(c + 1) & 1] + bo, acc, SAc * 2);
    }
    __syncthreads();
    cpaB(w3, 128, 0, sbB[1], tid);                      // cc5 -> buf1
    epi_act(acc, b2, smc, SAc, w, lane);                // act2 -> cols 0-127
    zero_acc(acc);
    for (int c = 0; c < 2; c++) {                       // cc 5,6 -> bufs 1,0
        CPA_W0(); __syncthreads();
        if (c < 1) cpaB(w3, 128, 64, sbB[0], tid);
        mma_chunk(aW + (uint32_t)(c * 64) * 2, sbB[(c + 1) & 1] + bo, acc, SAc * 2);
    }
    __syncthreads();
    cpaB(w1, 192, 0, sbB[1], tid);                      // cc7 -> buf1
    // LN -> xc1 (fp16) into smem cols 0-127
    epi_ln(acc, b3, gam, bet, s_red, rowbase, nrows, smc, SAc, nullptr, nullptr, nullptr, w, lane);

    // ---- ROUND 2 ----  (xc1 cols 0-127, agg cols 128-191 still resident)
    zero_acc(acc);
    for (int c = 0; c < 3; c++) {                       // cc 7,8,9 -> bufs 1,0,1
        CPA_W0(); __syncthreads();
        if (c < 2) cpaB(w1, 192, (c + 1) * 64, sbB[c & 1], tid);
        mma_chunk(aW + (uint32_t)(c * 64) * 2, sbB[(c + 1) & 1] + bo, acc, SAc * 2);
    }
    __syncthreads();
    cpaB(w2, 128, 0, sbB[0], tid);                      // cc10 -> buf0
    epi_act(acc, b1, smc, SAc, w, lane);
    zero_acc(acc);
    for (int c = 0; c < 2; c++) {                       // cc 10,11 -> bufs 0,1
        CPA_W0(); __syncthreads();
        if (c < 1) cpaB(w2, 128, 64, sbB[1], tid);
        mma_chunk(aW + (uint32_t)(c * 64) * 2, sbB[c & 1] + bo, acc, SAc * 2);
    }
    __syncthreads();
    cpaB(w3, 128, 0, sbB[0], tid);                      // cc12 -> buf0
    epi_act(acc, b2, smc, SAc, w, lane);
    zero_acc(acc);
    for (int c = 0; c < 2; c++) {                       // cc 12,13 -> bufs 0,1
        CPA_W0(); __syncthreads();
        if (c < 1) cpaB(w3, 128, 64, sbB[1], tid);
        mma_chunk(aW + (uint32_t)(c * 64) * 2, sbB[c & 1] + bo, acc, SAc * 2);
    }
    __syncthreads();
    // final LN: out_x = x + LN, xc2h = LN (fp16)
    epi_ln(acc, b3, gam, bet, s_red, rowbase, nrows, nullptr, SAc, xc2h, x32, out_x, w, lane);
}

// ---------------- EdgeBlock: [ea | xc[s] | xc[r]](384) -> 128 -> 128 -> LN ----------------
__global__ void __launch_bounds__(T, 3) k_edge(
    const __half* __restrict__ eah, const float* __restrict__ ea32,
    const __half* __restrict__ xch, const int* __restrict__ ei,
    const __half* __restrict__ w1, const __half* __restrict__ w2, const __half* __restrict__ w3,
    const float* __restrict__ b1, const float* __restrict__ b2, const float* __restrict__ b3,
    const float* __restrict__ gam, const float* __restrict__ bet,
    float* out2, int E)
{
    extern __shared__ char smc[];
    uint32_t sa = smem_u32(smc);
    uint32_t sbB[2] = { sa + E_B0, sa + E_B1 };
    float* s_red = (float*)(smc + E_RED);
    int tid = threadIdx.x, w = tid >> 5, lane = tid & 31;
    int rowbase = blockIdx.x * 64;
    int arow = (lane & 7) + ((lane >> 3) & 1) * 8;
    int acol = (lane >> 4) * 8;
    int b_r = (lane & 7) + (lane >> 4) * 8;
    int b_c = ((lane >> 3) & 1) * 8;
    int rg = w & 1;
    uint32_t aW = sa + (uint32_t)((rg * 32 + arow) * SAe + acol) * 2;
    uint32_t bo = (uint32_t)(((w >> 1) * 64 + b_r) * SB + b_c) * 2;
    float acc[2][8][4];

    // layer1: K=384, 6 chunks; A segs ping-pong: seg0(ea)->cols0-127, seg1(xc[s])->128-255, seg2(xc[r])->0-127
    cpaH(eah, Hdim, 16, rowbase, E, sa, SAe, tid);
    cpaB(w1, 384, 0, sbB[0], tid);
    zero_acc(acc);
    for (int c = 0; c < 6; c++) {
        if (c == 1 || c == 3) { CPA_W1(); } else { CPA_W0(); }
        __syncthreads();
        if (c < 5) cpaB(w1, 384, (c + 1) * 64, sbB[(c + 1) & 1], tid);
        if (c == 0) cpaGh(xch, ei,     rowbase, sa + 128u * 2, SAe, tid);
        if (c == 2) cpaGh(xch, ei + E, rowbase, sa, SAe, tid);
        uint32_t aoff = (uint32_t)((((c >> 1) & 1) * 128) + (c & 1) * 64) * 2;
        mma_chunk(aW + aoff, sbB[c & 1] + bo, acc, SAe * 2);
    }
    __syncthreads();
    cpaB(w2, 128, 0, sbB[0], tid);
    epi_act(acc, b1, smc, SAe, w, lane);
    zero_acc(acc);
    for (int c = 0; c < 2; c++) {
        CPA_W0(); __syncthreads();
        if (c < 1) cpaB(w2, 128, 64, sbB[1], tid);
        mma_chunk(aW + (uint32_t)(c * 64) * 2, sbB[c & 1] + bo, acc, SAe * 2);
    }
    __syncthreads();
    cpaB(w3, 128, 0, sbB[0], tid);
    epi_act(acc, b2, smc, SAe, w, lane);
    zero_acc(acc);
    for (int c = 0; c < 2; c++) {
        CPA_W0(); __syncthreads();
        if (c < 1) cpaB(w3, 128, 64, sbB[1], tid);
        mma_chunk(aW + (uint32_t)(c * 64) * 2, sbB[c & 1] + bo, acc, SAe * 2);
    }
    __syncthreads();
    epi_ln(acc, b3, gam, bet, s_red, rowbase, E, nullptr, SAe, nullptr, ea32, out2, w, lane);
}

// ---------------- host ----------------
extern "C" void kernel_launch(void* const* d_in, const int* in_sizes, int n_in,
                              void* d_out, int out_size)
{
    const float* x     = (const float*)d_in[0];
    const float* ea    = (const float*)d_in[1];
    const float* cb_w1 = (const float*)d_in[2];
    const float* cb_b1 = (const float*)d_in[3];
    const float* cb_w2 = (const float*)d_in[4];
    const float* cb_b2 = (const float*)d_in[5];
    const float* cb_w3 = (const float*)d_in[6];
    const float* cb_b3 = (const float*)d_in[7];
    const float* cb_g  = (const float*)d_in[8];
    const float* cb_be = (const float*)d_in[9];
    const float* eb_w1 = (const float*)d_in[10];
    const float* eb_b1 = (const float*)d_in[11];
    const float* eb_w2 = (const float*)d_in[12];
    const float* eb_b2 = (const float*)d_in[13];
    const float* eb_w3 = (const float*)d_in[14];
    const float* eb_b3 = (const float*)d_in[15];
    const float* eb_g  = (const float*)d_in[16];
    const float* eb_be = (const float*)d_in[17];
    const int*   ei    = (const int*)d_in[18];

    int N = in_sizes[0] / Hdim;
    int E = in_sizes[1] / Hdim;
    float* out_x = (float*)d_out;
    float* out_e = out_x + (size_t)N * Hdim;

    __half *xh, *aggh, *xc2h, *eah, *wt;
    float* agg;
    cudaGetSymbolAddress((void**)&xh, g_xh);
    cudaGetSymbolAddress((void**)&aggh, g_aggh);
    cudaGetSymbolAddress((void**)&xc2h, g_xc2h);
    cudaGetSymbolAddress((void**)&eah, g_eah);
    cudaGetSymbolAddress((void**)&wt, g_wt);
    cudaGetSymbolAddress((void**)&agg, g_agg);

    cudaFuncSetAttribute(k_cell, cudaFuncAttributeMaxDynamicSharedMemorySize, SMEM_CELL);
    cudaFuncSetAttribute(k_edge, cudaFuncAttributeMaxDynamicSharedMemorySize, SMEM_EDGE);

    const int OCB1 = 0, OCB2 = 24576, OCB3 = 40960, OEB1 = 57344, OEB2 = 106496, OEB3 = 122880;

    k_prep_all<<<(139264 + 255) / 256, 256>>>(cb_w1, cb_w2, cb_w3, eb_w1, eb_w2, eb_w3);
    k_init<<<(N * 32 + 255) / 256, 256>>>(x, N);
    k_scatter<<<(E * 32 + 255) / 256, 256>>>(ea, ei, E);
    k_cvt<<<(N * 16 + 255) / 256, 256>>>(agg, aggh, N * 16);

    int cgrid = (N + 63) / 64;
    int egrid = (E + 63) / 64;

    k_cell<<<cgrid, T, SMEM_CELL>>>(xh, aggh, wt + OCB1, wt + OCB2, wt + OCB3,
        cb_b1, cb_b2, cb_b3, cb_g, cb_be, x, out_x, xc2h, N);

    k_edge<<<egrid, T, SMEM_EDGE>>>(eah, ea, xc2h, ei, wt + OEB1, wt + OEB2, wt + OEB3,
        eb_b1, eb_b2, eb_b3, eb_g, eb_be, out_e, E);
}

// round 11
// speedup vs baseline: 1.0814x; 1.0814x over previous
#include <cuda_runtime.h>
#include <cuda_fp16.h>
#include <cstdint>

#define Hdim 128
#define HALF 64
#define NMAX 200000
#define EMAX 400000
#define T 128
#define SAc 200             // cell A stride (fp16): 400B ≡ 16 mod 128 → conflict-free ldsm
#define SAe 264             // edge A stride: 528B ≡ 16 mod 128
#define SB 72               // B slice stride: 144B ≡ 16 mod 128
#define SBW 4608            // one B slice buffer: 32 rows x 72 halfs x 2B
// cell smem: A(64x200x2)=25600 | B 4 warps x 2 bufs x 4608 = 36864 | red 2048
#define C_B 25600
#define C_RED 62464
#define SMEM_CELL 64512
// edge smem: A(64x264x2)=33792 | B 36864 | red 2048
#define E_B 33792
#define E_RED 70656
#define SMEM_EDGE 72704

// ---------------- static device scratch ----------------
__device__ float  g_agg[(size_t)NMAX * HALF];
__device__ __half g_aggh[(size_t)NMAX * HALF];
__device__ __half g_xh[(size_t)NMAX * Hdim];
__device__ __half g_xc2h[(size_t)NMAX * Hdim];
__device__ __half g_eah[(size_t)EMAX * Hdim];
// transposed fp16 weights [n=128][K]; cb1:0 cb2:24576 cb3:40960 eb1:57344 eb2:106496 eb3:122880
__device__ __half g_wt[139264];

// ---------------- helpers ----------------
__device__ __forceinline__ uint32_t smem_u32(const void* p) {
    uint32_t a;
    asm("{ .reg .u64 t; cvta.to.shared.u64 t, %1; cvt.u32.u64 %0, t; }" : "=r"(a) : "l"(p));
    return a;
}
__device__ __forceinline__ void ldsm4(uint32_t r[4], uint32_t a) {
    asm volatile("ldmatrix.sync.aligned.m8n8.x4.shared.b16 {%0,%1,%2,%3}, [%4];"
        : "=r"(r[0]), "=r"(r[1]), "=r"(r[2]), "=r"(r[3]) : "r"(a));
}
__device__ __forceinline__ void mma16(float d[4], const uint32_t a[4], uint32_t b0, uint32_t b1) {
    asm volatile("mma.sync.aligned.m16n8k16.row.col.f32.f16.f16.f32 "
        "{%0,%1,%2,%3}, {%4,%5,%6,%7}, {%8,%9}, {%0,%1,%2,%3};"
        : "+f"(d[0]), "+f"(d[1]), "+f"(d[2]), "+f"(d[3])
        : "r"(a[0]), "r"(a[1]), "r"(a[2]), "r"(a[3]), "r"(b0), "r"(b1));
}
__device__ __forceinline__ float silu_f(float v) { return v * (1.0f / (1.0f + __expf(-v))); }
#define CPA16(dst, src) asm volatile("cp.async.cg.shared.global [%0], [%1], 16;" :: "r"(dst), "l"(src) : "memory")
#define CPA_COMMIT() asm volatile("cp.async.commit_group;" ::: "memory")
#define CPA_W0() asm volatile("cp.async.wait_group 0;" ::: "memory")
#define CPA_W1() asm volatile("cp.async.wait_group 1;" ::: "memory")
#define CPA_W2() asm volatile("cp.async.wait_group 2;" ::: "memory")

// ---------------- small kernels ----------------
__global__ void k_init(const float* __restrict__ x, int N) {
    int i = blockIdx.x * blockDim.x + threadIdx.x;
    int nz = N * 16;
    if (i < nz) ((float4*)g_agg)[i] = make_float4(0.f, 0.f, 0.f, 0.f);
    int nc = N * 32;
    if (i < nc) {
        float4 v = ((const float4*)x)[i];
        half2 h0 = __floats2half2_rn(v.x, v.y);
        half2 h1 = __floats2half2_rn(v.z, v.w);
        *(uint2*)(g_xh + (size_t)i * 4) = make_uint2(*(uint32_t*)&h0, *(uint32_t*)&h1);
    }
}
__global__ void k_cvt(const float* __restrict__ src, __half* __restrict__ dst, int n4) {
    int i = blockIdx.x * blockDim.x + threadIdx.x;
    if (i >= n4) return;
    float4 v = ((const float4*)src)[i];
    half2 h0 = __floats2half2_rn(v.x, v.y);
    half2 h1 = __floats2half2_rn(v.z, v.w);
    *(uint2*)(dst + (size_t)i * 4) = make_uint2(*(uint32_t*)&h0, *(uint32_t*)&h1);
}
__global__ void k_scatter(const float* __restrict__ ea, const int* __restrict__ ei, int E) {
    int gid = blockIdx.x * blockDim.x + threadIdx.x;
    int e = gid >> 5;
    if (e >= E) return;
    int c4 = (gid & 31) << 2;
    float4 v = *(const float4*)(ea + (size_t)e * Hdim + c4);
    half2 h0 = __floats2half2_rn(v.x, v.y);
    half2 h1 = __floats2half2_rn(v.z, v.w);
    *(uint2*)(g_eah + (size_t)e * Hdim + c4) = make_uint2(*(uint32_t*)&h0, *(uint32_t*)&h1);
    float* base;
    if (c4 < HALF) { int r = ei[E + e]; base = g_agg + (size_t)r * HALF + c4; }
    else           { int s = ei[e];     base = g_agg + (size_t)s * HALF + (c4 - HALF); }
    asm volatile("red.global.add.v4.f32 [%0], {%1,%2,%3,%4};"
        :: "l"(base), "f"(v.x), "f"(v.y), "f"(v.z), "f"(v.w) : "memory");
}
__global__ void k_prep_all(const float* cw1, const float* cw2, const float* cw3,
                           const float* ew1, const float* ew2, const float* ew3) {
    int idx = blockIdx.x * blockDim.x + threadIdx.x;
    if (idx >= 139264) return;
    const float* src; int K, off;
    if      (idx < 24576)  { src = cw1; K = 192; off = 0; }
    else if (idx < 40960)  { src = cw2; K = 128; off = 24576; }
    else if (idx < 57344)  { src = cw3; K = 128; off = 40960; }
    else if (idx < 106496) { src = ew1; K = 384; off = 57344; }
    else if (idx < 122880) { src = ew2; K = 128; off = 106496; }
    else                   { src = ew3; K = 128; off = 122880; }
    int l = idx - off;
    int n = l / K, k = l - n * K;
    g_wt[idx] = __float2half(src[k * Hdim + n]);
}

// ---------------- staging ----------------
// block-wide A staging (commits one group)
__device__ __forceinline__ void cpaH(const __half* __restrict__ src, int ld, int ncol8,
                                     int rowbase, int nrows, uint32_t dstbase, int strideH, int tid) {
    int tot = 64 * ncol8;
    for (int idx = tid; idx < tot; idx += T) {
        int r = idx / ncol8, c8 = (idx - r * ncol8) * 8;
        int grow = rowbase + r; if (grow >= nrows) grow = nrows - 1;
        CPA16(dstbase + (uint32_t)(r * strideH + c8) * 2, src + (size_t)grow * ld + c8);
    }
    CPA_COMMIT();
}
__device__ __forceinline__ void cpaGh(const __half* __restrict__ src, const int* __restrict__ eidx,
                                      int rowbase, int nrows, uint32_t dstbase, int strideH, int tid) {
#pragma unroll
    for (int i = 0; i < 8; i++) {
        int idx = tid + i * T;
        int r = idx >> 4, c8 = (idx & 15) * 8;
        int grow = rowbase + r; if (grow >= nrows) grow = nrows - 1;
        int srow = __ldg(eidx + grow);
        CPA16(dstbase + (uint32_t)(r * strideH + c8) * 2, src + (size_t)srow * Hdim + c8);
    }
    CPA_COMMIT();
}
// per-warp private B slice: this warp's 32 n-rows x 64 k-cols
__device__ __forceinline__ void cpaBs(const __half* __restrict__ wt, int K, int k0,
                                      uint32_t dstbase, int w, int lane) {
#pragma unroll
    for (int i = 0; i < 8; i++) {
        int idx = lane + i * 32;
        int n = idx >> 3, c8 = (idx & 7) * 8;
        CPA16(dstbase + (uint32_t)(n * SB + c8) * 2, wt + (size_t)(w * 32 + n) * K + k0 + c8);
    }
    CPA_COMMIT();
}

// ---------------- MMA: warp = 64 rows x 32 cols over one 64-K chunk ----------------
__device__ __forceinline__ void mma_chunk64(uint32_t aB, uint32_t bB, float acc[4][4][4], int strideAB) {
#pragma unroll
    for (int ks = 0; ks < 4; ks++) {
        uint32_t A[4][4];
#pragma unroll
        for (int mt = 0; mt < 4; mt++) ldsm4(A[mt], aB + mt * 16 * strideAB + ks * 32);
#pragma unroll
        for (int p = 0; p < 2; p++) {
            uint32_t B[4];
            ldsm4(B, bB + p * 16 * (SB * 2) + ks * 32);
#pragma unroll
            for (int mt = 0; mt < 4; mt++) {
                mma16(acc[mt][2 * p],     A[mt], B[0], B[1]);
                mma16(acc[mt][2 * p + 1], A[mt], B[2], B[3]);
            }
        }
    }
}
__device__ __forceinline__ void zero_acc(float acc[4][4][4]) {
#pragma unroll
    for (int m = 0; m < 4; m++)
#pragma unroll
        for (int t = 0; t < 4; t++)
#pragma unroll
            for (int i = 0; i < 4; i++) acc[m][t][i] = 0.0f;
}

// ---------------- epilogues (warp w owns rows 0-63 x cols [w*32, w*32+32)) ----------------
__device__ __forceinline__ void epi_act(float acc[4][4][4], const float* __restrict__ bias,
                                        char* smA, int strideH, int w, int lane) {
    int c2 = (lane & 3) * 2, r0 = lane >> 2;
#pragma unroll
    for (int mt = 0; mt < 4; mt++)
#pragma unroll
        for (int nt = 0; nt < 4; nt++) {
            int col = w * 32 + nt * 8 + c2;
            float2 b = __ldg((const float2*)(bias + col));
            int row = mt * 16 + r0;
            half2 h0 = __floats2half2_rn(silu_f(acc[mt][nt][0] + b.x), silu_f(acc[mt][nt][1] + b.y));
            *(half2*)(smA + ((size_t)(row * strideH + col)) * 2) = h0;
            half2 h1 = __floats2half2_rn(silu_f(acc[mt][nt][2] + b.x), silu_f(acc[mt][nt][3] + b.y));
            *(half2*)(smA + ((size_t)((row + 8) * strideH + col)) * 2) = h1;
        }
}
// LN: smA != null -> fp16 LN to smem cols 0-127; else gmem (out1h fp16 copy, out2 = resid + LN)
__device__ __forceinline__ void epi_ln(float acc[4][4][4],
    const float* __restrict__ bias, const float* __restrict__ gam, const float* __restrict__ bet,
    float* s_red, int rowbase, int nrows, char* smA, int strideH,
    __half* out1h, const float* __restrict__ resid, float* out2, int w, int lane)
{
    int c2 = (lane & 3) * 2, r0 = lane >> 2;
    float vals[4][2][8];
#pragma unroll
    for (int mt = 0; mt < 4; mt++)
#pragma unroll
        for (int nt = 0; nt < 4; nt++) {
            int col = w * 32 + nt * 8 + c2;
            float2 b = __ldg((const float2*)(bias + col));
            vals[mt][0][2 * nt]     = acc[mt][nt][0] + b.x;
            vals[mt][0][2 * nt + 1] = acc[mt][nt][1] + b.y;
            vals[mt][1][2 * nt]     = acc[mt][nt][2] + b.x;
            vals[mt][1][2 * nt + 1] = acc[mt][nt][3] + b.y;
        }
#pragma unroll
    for (int mt = 0; mt < 4; mt++)
#pragma unroll
        for (int h = 0; h < 2; h++) {
            float s = 0.0f, q = 0.0f;
#pragma unroll
            for (int j = 0; j < 8; j++) { float v = vals[mt][h][j]; s += v; q += v * v; }
            s += __shfl_xor_sync(0xffffffffu, s, 1);
            q += __shfl_xor_sync(0xffffffffu, q, 1);
            s += __shfl_xor_sync(0xffffffffu, s, 2);
            q += __shfl_xor_sync(0xffffffffu, q, 2);
            int r = mt * 16 + h * 8 + r0;
            if ((lane & 3) == 0) {
                s_red[w * 64 + r] = s;
                s_red[256 + w * 64 + r] = q;
            }
        }
    __syncthreads();
#pragma unroll
    for (int mt = 0; mt < 4; mt++)
#pragma unroll
        for (int h = 0; h < 2; h++) {
            int r = mt * 16 + h * 8 + r0;
            float st = s_red[r] + s_red[64 + r] + s_red[128 + r] + s_red[192 + r];
            float qt = s_red[256 + r] + s_red[320 + r] + s_red[384 + r] + s_red[448 + r];
            float mu = st * (1.0f / Hdim);
            float inv = rsqrtf(qt * (1.0f / Hdim) - mu * mu + 1e-5f);
            int grow = rowbase + r;
#pragma unroll
            for (int nt = 0; nt < 4; nt++) {
                int col = w * 32 + nt * 8 + c2;
                float2 g = __ldg((const float2*)(gam + col));
                float2 b = __ldg((const float2*)(bet + col));
                float2 o;
                o.x = (vals[mt][h][2 * nt]     - mu) * inv * g.x + b.x;
                o.y = (vals[mt][h][2 * nt + 1] - mu) * inv * g.y + b.y;
                if (smA) {
                    *(half2*)(smA + ((size_t)(r * strideH + col)) * 2) = __floats2half2_rn(o.x, o.y);
                } else if (grow < nrows) {
                    size_t base = (size_t)grow * Hdim + col;
                    if (out1h) *(half2*)(out1h + base) = __floats2half2_rn(o.x, o.y);
                    if (out2) {
                        float2 rv = *(const float2*)(resid + base);
                        *(float2*)(out2 + base) = make_float2(o.x + rv.x, o.y + rv.y);
                    }
                }
            }
        }
}

// ---------------- fused CellBlock: both mp rounds ----------------
__global__ void __launch_bounds__(T, 3) k_cell(
    const __half* __restrict__ xh, const __half* __restrict__ aggh,
    const __half* __restrict__ w1, const __half* __restrict__ w2, const __half* __restrict__ w3,
    const float* __restrict__ b1, const float* __restrict__ b2, const float* __restrict__ b3,
    const float* __restrict__ gam, const float* __restrict__ bet,
    const float* __restrict__ x32, float* __restrict__ out_x, __half* __restrict__ xc2h,
    int nrows)
{
    extern __shared__ char smc[];
    uint32_t sa = smem_u32(smc);
    float* s_red = (float*)(smc + C_RED);
    int tid = threadIdx.x, w = tid >> 5, lane = tid & 31;
    int rowbase = blockIdx.x * 64;
    int arow = (lane & 7) + ((lane >> 3) & 1) * 8;
    int acol = (lane >> 4) * 8;
    int b_r = (lane & 7) + (lane >> 4) * 8;
    int b_c = ((lane >> 3) & 1) * 8;
    uint32_t aW  = sa + (uint32_t)(arow * SAc + acol) * 2;
    uint32_t sbW = sa + C_B + (uint32_t)w * (2 * SBW);
    uint32_t bo  = (uint32_t)(b_r * SB + b_c) * 2;
    float acc[4][4][4];
    int cc = 0;   // global chunk counter -> buffer parity

    // prologue: A (x cols0-127, agg cols128-191), B chunk0 of W1
    cpaH(xh, Hdim, 16, rowbase, nrows, sa, SAc, tid);
    cpaH(aggh, HALF, 8, rowbase, nrows, sa + 128u * 2, SAc, tid);
    cpaBs(w1, 192, 0, sbW, w, lane);
    CPA_W1();                 // A groups done; W1c0 in flight
    __syncthreads();

#pragma unroll 1
    for (int rnd = 0; rnd < 2; rnd++) {
        // ---- L1: 3 chunks (A cols 0,64,128) ----
        zero_acc(acc);
        cpaBs(w1, 192, 64, sbW + ((cc + 1) & 1) * SBW, w, lane);
        CPA_W1(); __syncwarp();
        mma_chunk64(aW, sbW + (cc & 1) * SBW + bo, acc, SAc * 2); cc++;
        cpaBs(w1, 192, 128, sbW + ((cc + 1) & 1) * SBW, w, lane);
        CPA_W1(); __syncwarp();
        mma_chunk64(aW + 64 * 2, sbW + (cc & 1) * SBW + bo, acc, SAc * 2); cc++;
        cpaBs(w2, 128, 0, sbW + ((cc + 1) & 1) * SBW, w, lane);
        CPA_W1(); __syncwarp();
        mma_chunk64(aW + 128 * 2, sbW + (cc & 1) * SBW + bo, acc, SAc * 2); cc++;
        __syncthreads();
        epi_act(acc, b1, smc, SAc, w, lane);
        __syncthreads();
        // ---- L2: 2 chunks (A cols 0,64) ----
        zero_acc(acc);
        cpaBs(w2, 128, 64, sbW + ((cc + 1) & 1) * SBW, w, lane);
        CPA_W1(); __syncwarp();
        mma_chunk64(aW, sbW + (cc & 1) * SBW + bo, acc, SAc * 2); cc++;
        cpaBs(w3, 128, 0, sbW + ((cc + 1) & 1) * SBW, w, lane);
        CPA_W1(); __syncwarp();
        mma_chunk64(aW + 64 * 2, sbW + (cc & 1) * SBW + bo, acc, SAc * 2); cc++;
        __syncthreads();
        epi_act(acc, b2, smc, SAc, w, lane);
        __syncthreads();
        // ---- L3: 2 chunks ----
        zero_acc(acc);
        cpaBs(w3, 128, 64, sbW + ((cc + 1) & 1) * SBW, w, lane);
        CPA_W1(); __syncwarp();
        mma_chunk64(aW, sbW + (cc & 1) * SBW + bo, acc, SAc * 2); cc++;
        if (rnd == 0) {
            cpaBs(w1, 192, 0, sbW + ((cc + 1) & 1) * SBW, w, lane);  // round-2 W1c0
            CPA_W1();
        } else {
            CPA_W0();
        }
        __syncwarp();
        mma_chunk64(aW + 64 * 2, sbW + (cc & 1) * SBW + bo, acc, SAc * 2); cc++;
        __syncthreads();
        if (rnd == 0) {
            // LN -> xc1 fp16 into A cols 0-127 (agg at 128-191 stays)
            epi_ln(acc, b3, gam, bet, s_red, rowbase, nrows, smc, SAc,
                   nullptr, nullptr, nullptr, w, lane);
            __syncthreads();
        } else {
            epi_ln(acc, b3, gam, bet, s_red, rowbase, nrows, nullptr, SAc,
                   xc2h, x32, out_x, w, lane);
        }
    }
}

// ---------------- EdgeBlock: [ea | xc[s] | xc[r]](384) -> 128 -> 128 -> LN ----------------
__global__ void __launch_bounds__(T, 3) k_edge(
    const __half* __restrict__ eah, const float* __restrict__ ea32,
    const __half* __restrict__ xch, const int* __restrict__ ei,
    const __half* __restrict__ w1, const __half* __restrict__ w2, const __half* __restrict__ w3,
    const float* __restrict__ b1, const float* __restrict__ b2, const float* __restrict__ b3,
    const float* __restrict__ gam, const float* __restrict__ bet,
    float* __restrict__ out_e, int E)
{
    extern __shared__ char smc[];
    uint32_t sa = smem_u32(smc);
    float* s_red = (float*)(smc + E_RED);
    int tid = threadIdx.x, w = tid >> 5, lane = tid & 31;
    int rowbase = blockIdx.x * 64;
    int arow = (lane & 7) + ((lane >> 3) & 1) * 8;
    int acol = (lane >> 4) * 8;
    int b_r = (lane & 7) + (lane >> 4) * 8;
    int b_c = ((lane >> 3) & 1) * 8;
    uint32_t aW  = sa + (uint32_t)(arow * SAe + acol) * 2;
    uint32_t sbW = sa + E_B + (uint32_t)w * (2 * SBW);
    uint32_t bo  = (uint32_t)(b_r * SB + b_c) * 2;
    float acc[4][4][4];
    int cc = 0;

    // prologue: ea -> cols 0-127 (gA), W1c0 (g0), gather1 -> cols 128-255 (gG1)
    cpaH(eah, Hdim, 16, rowbase, E, sa, SAe, tid);
    cpaBs(w1, 384, 0, sbW, w, lane);
    cpaGh(xch, ei, rowbase, E, sa + 128u * 2, SAe, tid);
    CPA_W1();                 // gA + g0 done; gG1 in flight
    __syncthreads();

    // ---- L1: 6 chunks ----
    zero_acc(acc);
    // c0 (ea cols 0)
    cpaBs(w1, 384, 64, sbW + ((cc + 1) & 1) * SBW, w, lane);
    CPA_W1(); __syncwarp();                                   // completes gG1
    mma_chunk64(aW, sbW + (cc & 1) * SBW + bo, acc, SAe * 2); cc++;
    // c1 (ea cols 64)
    cpaBs(w1, 384, 128, sbW + ((cc + 1) & 1) * SBW, w, lane);
    CPA_W1(); __syncwarp();
    mma_chunk64(aW + 64 * 2, sbW + (cc & 1) * SBW + bo, acc, SAe * 2); cc++;
    // seg swap: all warps done with cols 0-127; gG1 visible (waited by every thread at c0)
    __syncthreads();
    cpaGh(xch, ei + E, rowbase, E, sa, SAe, tid);             // gather2 -> cols 0-127 (gG2)
    // c2 (xc[s] cols 128)
    cpaBs(w1, 384, 192, sbW + ((cc + 1) & 1) * SBW, w, lane);
    CPA_W2(); __syncwarp();                                   // completes g2; gG2+g3 fly
    mma_chunk64(aW + 128 * 2, sbW + (cc & 1) * SBW + bo, acc, SAe * 2); cc++;
    // c3 (xc[s] cols 192)
    cpaBs(w1, 384, 256, sbW + ((cc + 1) & 1) * SBW, w, lane);
    CPA_W1(); __syncwarp();                                   // completes gG2 + g3
    mma_chunk64(aW + 192 * 2, sbW + (cc & 1) * SBW + bo, acc, SAe * 2); cc++;
    __syncthreads();                                          // gG2 visible to all
    // c4 (xc[r] cols 0)
    cpaBs(w1, 384, 320, sbW + ((cc + 1) & 1) * SBW, w, lane);
    CPA_W1(); __syncwarp();
    mma_chunk64(aW, sbW + (cc & 1) * SBW + bo, acc, SAe * 2); cc++;
    // c5 (xc[r] cols 64)
    cpaBs(w2, 128, 0, sbW + ((cc + 1) & 1) * SBW, w, lane);
    CPA_W1(); __syncwarp();
    mma_chunk64(aW + 64 * 2, sbW + (cc & 1) * SBW + bo, acc, SAe * 2); cc++;
    __syncthreads();
    epi_act(acc, b1, smc, SAe, w, lane);
    __syncthreads();
    // ---- L2 ----
    zero_acc(acc);
    cpaBs(w2, 128, 64, sbW + ((cc + 1) & 1) * SBW, w, lane);
    CPA_W1(); __syncwarp();
    mma_chunk64(aW, sbW + (cc & 1) * SBW + bo, acc, SAe * 2); cc++;
    cpaBs(w3, 128, 0, sbW + ((cc + 1) & 1) * SBW, w, lane);
    CPA_W1(); __syncwarp();
    mma_chunk64(aW + 64 * 2, sbW + (cc & 1) * SBW + bo, acc, SAe * 2); cc++;
    __syncthreads();
    epi_act(acc, b2, smc, SAe, w, lane);
    __syncthreads();
    // ---- L3 ----
    zero_acc(acc);
    cpaBs(w3, 128, 64, sbW + ((cc + 1) & 1) * SBW, w, lane);
    CPA_W1(); __syncwarp();
    mma_chunk64(aW, sbW + (cc & 1) * SBW + bo, acc, SAe * 2); cc++;
    CPA_W0(); __syncwarp();
    mma_chunk64(aW + 64 * 2, sbW + (cc & 1) * SBW + bo, acc, SAe * 2); cc++;
    __syncthreads();
    epi_ln(acc, b3, gam, bet, s_red, rowbase, E, nullptr, SAe, nullptr, ea32, out_e, w, lane);
}

// ---------------- host ----------------
extern "C" void kernel_launch(void* const* d_in, const int* in_sizes, int n_in,
                              void* d_out, int out_size)
{
    const float* x     = (const float*)d_in[0];
    const float* ea    = (const float*)d_in[1];
    const float* cb_w1 = (const float*)d_in[2];
    const float* cb_b1 = (const float*)d_in[3];
    const float* cb_w2 = (const float*)d_in[4];
    const float* cb_b2 = (const float*)d_in[5];
    const float* cb_w3 = (const float*)d_in[6];
    const float* cb_b3 = (const float*)d_in[7];
    const float* cb_g  = (const float*)d_in[8];
    const float* cb_be = (const float*)d_in[9];
    const float* eb_w1 = (const float*)d_in[10];
    const float* eb_b1 = (const float*)d_in[11];
    const float* eb_w2 = (const float*)d_in[12];
    const float* eb_b2 = (const float*)d_in[13];
    const float* eb_w3 = (const float*)d_in[14];
    const float* eb_b3 = (const float*)d_in[15];
    const float* eb_g  = (const float*)d_in[16];
    const float* eb_be = (const float*)d_in[17];
    const int*   ei    = (const int*)d_in[18];

    int N = in_sizes[0] / Hdim;
    int E = in_sizes[1] / Hdim;
    float* out_x = (float*)d_out;
    float* out_e = out_x + (size_t)N * Hdim;

    __half *xh, *aggh, *xc2h, *eah, *wt;
    float* agg;
    cudaGetSymbolAddress((void**)&xh, g_xh);
    cudaGetSymbolAddress((void**)&aggh, g_aggh);
    cudaGetSymbolAddress((void**)&xc2h, g_xc2h);
    cudaGetSymbolAddress((void**)&eah, g_eah);
    cudaGetSymbolAddress((void**)&wt, g_wt);
    cudaGetSymbolAddress((void**)&agg, g_agg);

    cudaFuncSetAttribute(k_cell, cudaFuncAttributeMaxDynamicSharedMemorySize, SMEM_CELL);
    cudaFuncSetAttribute(k_edge, cudaFuncAttributeMaxDynamicSharedMemorySize, SMEM_EDGE);

    const int OCB1 = 0, OCB2 = 24576, OCB3 = 40960, OEB1 = 57344, OEB2 = 106496, OEB3 = 122880;

    k_prep_all<<<(139264 + 255) / 256, 256>>>(cb_w1, cb_w2, cb_w3, eb_w1, eb_w2, eb_w3);
    k_init<<<(N * 32 + 255) / 256, 256>>>(x, N);
    k_scatter<<<(E * 32 + 255) / 256, 256>>>(ea, ei, E);
    k_cvt<<<(N * 16 + 255) / 256, 256>>>(agg, aggh, N * 16);

    int cgrid = (N + 63) / 64;
    int egrid = (E + 63) / 64;

    k_cell<<<cgrid, T, SMEM_CELL>>>(xh, aggh, wt + OCB1, wt + OCB2, wt + OCB3,
        cb_b1, cb_b2, cb_b3, cb_g, cb_be, x, out_x, xc2h, N);

    k_edge<<<egrid, T, SMEM_EDGE>>>(eah, ea, xc2h, ei, wt + OEB1, wt + OEB2, wt + OEB3,
        eb_b1, eb_b2, eb_b3, eb_g, eb_be, out_e, E);
}

// round 13
// speedup vs baseline: 1.1389x; 1.0531x over previous
#include <cuda_runtime.h>
#include <cuda_fp16.h>
#include <cstdint>

#define Hdim 128
#define HALF 64
#define NMAX 200000
#define EMAX 400000
#define T 128
#define SAc 200             // cell A stride (fp16): 400B ≡ 16 mod 128 → conflict-free ldsm
#define SAe 264             // edge A stride: 528B ≡ 16 mod 128
#define SB32 40             // B slice stride: 80B (16B-aligned; rows mod 128 all-distinct → conflict-free)
#define SBW 2560            // one B slice buffer: 32 rows x 40 halfs x 2B
// cell smem: A(64x200x2)=25600 | B 4 warps x 2 bufs x 2560 = 20480 | red 2048
#define C_B 25600
#define C_RED 46080
#define SMEM_CELL 48128
// edge smem: A(64x264x2)=33792 | B 20480 | red 2048
#define E_B 33792
#define E_RED 54272
#define SMEM_EDGE 56320

// ---------------- static device scratch ----------------
__device__ float  g_agg[(size_t)NMAX * HALF];
__device__ __half g_aggh[(size_t)NMAX * HALF];
__device__ __half g_xh[(size_t)NMAX * Hdim];
__device__ __half g_xc2h[(size_t)NMAX * Hdim];
__device__ __half g_eah[(size_t)EMAX * Hdim];
// transposed fp16 weights [n=128][K]; cb1:0 cb2:24576 cb3:40960 eb1:57344 eb2:106496 eb3:122880
__device__ __half g_wt[139264];

// ---------------- helpers ----------------
__device__ __forceinline__ uint32_t smem_u32(const void* p) {
    uint32_t a;
    asm("{ .reg .u64 t; cvta.to.shared.u64 t, %1; cvt.u32.u64 %0, t; }" : "=r"(a) : "l"(p));
    return a;
}
__device__ __forceinline__ void ldsm4(uint32_t r[4], uint32_t a) {
    asm volatile("ldmatrix.sync.aligned.m8n8.x4.shared.b16 {%0,%1,%2,%3}, [%4];"
        : "=r"(r[0]), "=r"(r[1]), "=r"(r[2]), "=r"(r[3]) : "r"(a));
}
__device__ __forceinline__ void mma16(float d[4], const uint32_t a[4], uint32_t b0, uint32_t b1) {
    asm volatile("mma.sync.aligned.m16n8k16.row.col.f32.f16.f16.f32 "
        "{%0,%1,%2,%3}, {%4,%5,%6,%7}, {%8,%9}, {%0,%1,%2,%3};"
        : "+f"(d[0]), "+f"(d[1]), "+f"(d[2]), "+f"(d[3])
        : "r"(a[0]), "r"(a[1]), "r"(a[2]), "r"(a[3]), "r"(b0), "r"(b1));
}
__device__ __forceinline__ float silu_f(float v) { return v * (1.0f / (1.0f + __expf(-v))); }
#define CPA16(dst, src) asm volatile("cp.async.cg.shared.global [%0], [%1], 16;" :: "r"(dst), "l"(src) : "memory")
#define CPA_COMMIT() asm volatile("cp.async.commit_group;" ::: "memory")
#define CPA_W0() asm volatile("cp.async.wait_group 0;" ::: "memory")
#define CPA_W1() asm volatile("cp.async.wait_group 1;" ::: "memory")
#define CPA_W2() asm volatile("cp.async.wait_group 2;" ::: "memory")

// ---------------- small kernels ----------------
__global__ void k_init(const float* __restrict__ x, int N) {
    int i = blockIdx.x * blockDim.x + threadIdx.x;
    int nz = N * 16;
    if (i < nz) ((float4*)g_agg)[i] = make_float4(0.f, 0.f, 0.f, 0.f);
    int nc = N * 32;
    if (i < nc) {
        float4 v = ((const float4*)x)[i];
        half2 h0 = __floats2half2_rn(v.x, v.y);
        half2 h1 = __floats2half2_rn(v.z, v.w);
        *(uint2*)(g_xh + (size_t)i * 4) = make_uint2(*(uint32_t*)&h0, *(uint32_t*)&h1);
    }
}
__global__ void k_cvt(const float* __restrict__ src, __half* __restrict__ dst, int n4) {
    int i = blockIdx.x * blockDim.x + threadIdx.x;
    if (i >= n4) return;
    float4 v = ((const float4*)src)[i];
    half2 h0 = __floats2half2_rn(v.x, v.y);
    half2 h1 = __floats2half2_rn(v.z, v.w);
    *(uint2*)(dst + (size_t)i * 4) = make_uint2(*(uint32_t*)&h0, *(uint32_t*)&h1);
}
__global__ void k_scatter(const float* __restrict__ ea, const int* __restrict__ ei, int E) {
    int gid = blockIdx.x * blockDim.x + threadIdx.x;
    int e = gid >> 5;
    if (e >= E) return;
    int c4 = (gid & 31) << 2;
    float4 v = *(const float4*)(ea + (size_t)e * Hdim + c4);
    half2 h0 = __floats2half2_rn(v.x, v.y);
    half2 h1 = __floats2half2_rn(v.z, v.w);
    *(uint2*)(g_eah + (size_t)e * Hdim + c4) = make_uint2(*(uint32_t*)&h0, *(uint32_t*)&h1);
    float* base;
    if (c4 < HALF) { int r = ei[E + e]; base = g_agg + (size_t)r * HALF + c4; }
    else           { int s = ei[e];     base = g_agg + (size_t)s * HALF + (c4 - HALF); }
    asm volatile("red.global.add.v4.f32 [%0], {%1,%2,%3,%4};"
        :: "l"(base), "f"(v.x), "f"(v.y), "f"(v.z), "f"(v.w) : "memory");
}
__global__ void k_prep_all(const float* cw1, const float* cw2, const float* cw3,
                           const float* ew1, const float* ew2, const float* ew3) {
    int idx = blockIdx.x * blockDim.x + threadIdx.x;
    if (idx >= 139264) return;
    const float* src; int K, off;
    if      (idx < 24576)  { src = cw1; K = 192; off = 0; }
    else if (idx < 40960)  { src = cw2; K = 128; off = 24576; }
    else if (idx < 57344)  { src = cw3; K = 128; off = 40960; }
    else if (idx < 106496) { src = ew1; K = 384; off = 57344; }
    else if (idx < 122880) { src = ew2; K = 128; off = 106496; }
    else                   { src = ew3; K = 128; off = 122880; }
    int l = idx - off;
    int n = l / K, k = l - n * K;
    g_wt[idx] = __float2half(src[k * Hdim + n]);
}

// ---------------- staging ----------------
__device__ __forceinline__ void cpaH(const __half* __restrict__ src, int ld, int ncol8,
                                     int rowbase, int nrows, uint32_t dstbase, int strideH, int tid) {
    int tot = 64 * ncol8;
    for (int idx = tid; idx < tot; idx += T) {
        int r = idx / ncol8, c8 = (idx - r * ncol8) * 8;
        int grow = rowbase + r; if (grow >= nrows) grow = nrows - 1;
        CPA16(dstbase + (uint32_t)(r * strideH + c8) * 2, src + (size_t)grow * ld + c8);
    }
    CPA_COMMIT();
}
__device__ __forceinline__ void cpaGh(const __half* __restrict__ src, const int* __restrict__ eidx,
                                      int rowbase, int nrows, uint32_t dstbase, int strideH, int tid) {
#pragma unroll
    for (int i = 0; i < 8; i++) {
        int idx = tid + i * T;
        int r = idx >> 4, c8 = (idx & 15) * 8;
        int grow = rowbase + r; if (grow >= nrows) grow = nrows - 1;
        int srow = __ldg(eidx + grow);
        CPA16(dstbase + (uint32_t)(r * strideH + c8) * 2, src + (size_t)srow * Hdim + c8);
    }
    CPA_COMMIT();
}
// per-warp private B slice: this warp's 32 n-rows x 32 k-cols (80B row stride, 16B-aligned)
__device__ __forceinline__ void cpaBs32(const __half* __restrict__ wt, int K, int k0,
                                        uint32_t dstbase, int w, int lane) {
#pragma unroll
    for (int i = 0; i < 4; i++) {
        int idx = lane + i * 32;
        int n = idx >> 2, c8 = (idx & 3) * 8;
        CPA16(dstbase + (uint32_t)(n * SB32 + c8) * 2, wt + (size_t)(w * 32 + n) * K + k0 + c8);
    }
    CPA_COMMIT();
}

// ---------------- MMA: warp = 64 rows x 32 cols over one 32-K chunk ----------------
__device__ __forceinline__ void mma_chunk32(uint32_t aB, uint32_t bB, float acc[4][4][4], int strideAB) {
#pragma unroll
    for (int ks = 0; ks < 2; ks++) {
        uint32_t A[4][4];
#pragma unroll
        for (int mt = 0; mt < 4; mt++) ldsm4(A[mt], aB + mt * 16 * strideAB + ks * 32);
#pragma unroll
        for (int p = 0; p < 2; p++) {
            uint32_t B[4];
            ldsm4(B, bB + p * 16 * (SB32 * 2) + ks * 32);
#pragma unroll
            for (int mt = 0; mt < 4; mt++) {
                mma16(acc[mt][2 * p],     A[mt], B[0], B[1]);
                mma16(acc[mt][2 * p + 1], A[mt], B[2], B[3]);
            }
        }
    }
}
__device__ __forceinline__ void zero_acc(float acc[4][4][4]) {
#pragma unroll
    for (int m = 0; m < 4; m++)
#pragma unroll
        for (int t = 0; t < 4; t++)
#pragma unroll
            for (int i = 0; i < 4; i++) acc[m][t][i] = 0.0f;
}

// ---------------- epilogues (warp w owns rows 0-63 x cols [w*32, w*32+32)) ----------------
__device__ __forceinline__ void epi_act(float acc[4][4][4], const float* __restrict__ bias,
                                        char* smA, int strideH, int w, int lane) {
    int c2 = (lane & 3) * 2, r0 = lane >> 2;
#pragma unroll
    for (int mt = 0; mt < 4; mt++)
#pragma unroll
        for (int nt = 0; nt < 4; nt++) {
            int col = w * 32 + nt * 8 + c2;
            float2 b = __ldg((const float2*)(bias + col));
            int row = mt * 16 + r0;
            half2 h0 = __floats2half2_rn(silu_f(acc[mt][nt][0] + b.x), silu_f(acc[mt][nt][1] + b.y));
            *(half2*)(smA + ((size_t)(row * strideH + col)) * 2) = h0;
            half2 h1 = __floats2half2_rn(silu_f(acc[mt][nt][2] + b.x), silu_f(acc[mt][nt][3] + b.y));
            *(half2*)(smA + ((size_t)((row + 8) * strideH + col)) * 2) = h1;
        }
}
__device__ __forceinline__ void epi_ln(float acc[4][4][4],
    const float* __restrict__ bias, const float* __restrict__ gam, const float* __restrict__ bet,
    float* s_red, int rowbase, int nrows, char* smA, int strideH,
    __half* out1h, const float* __restrict__ resid, float* out2, int w, int lane)
{
    int c2 = (lane & 3) * 2, r0 = lane >> 2;
    float vals[4][2][8];
#pragma unroll
    for (int mt = 0; mt < 4; mt++)
#pragma unroll
        for (int nt = 0; nt < 4; nt++) {
            int col = w * 32 + nt * 8 + c2;
            float2 b = __ldg((const float2*)(bias + col));
            vals[mt][0][2 * nt]     = acc[mt][nt][0] + b.x;
            vals[mt][0][2 * nt + 1] = acc[mt][nt][1] + b.y;
            vals[mt][1][2 * nt]     = acc[mt][nt][2] + b.x;
            vals[mt][1][2 * nt + 1] = acc[mt][nt][3] + b.y;
        }
#pragma unroll
    for (int mt = 0; mt < 4; mt++)
#pragma unroll
        for (int h = 0; h < 2; h++) {
            float s = 0.0f, q = 0.0f;
#pragma unroll
            for (int j = 0; j < 8; j++) { float v = vals[mt][h][j]; s += v; q += v * v; }
            s += __shfl_xor_sync(0xffffffffu, s, 1);
            q += __shfl_xor_sync(0xffffffffu, q, 1);
            s += __shfl_xor_sync(0xffffffffu, s, 2);
            q += __shfl_xor_sync(0xffffffffu, q, 2);
            int r = mt * 16 + h * 8 + r0;
            if ((lane & 3) == 0) {
                s_red[w * 64 + r] = s;
                s_red[256 + w * 64 + r] = q;
            }
        }
    __syncthreads();
#pragma unroll
    for (int mt = 0; mt < 4; mt++)
#pragma unroll
        for (int h = 0; h < 2; h++) {
            int r = mt * 16 + h * 8 + r0;
            float st = s_red[r] + s_red[64 + r] + s_red[128 + r] + s_red[192 + r];
            float qt = s_red[256 + r] + s_red[320 + r] + s_red[384 + r] + s_red[448 + r];
            float mu = st * (1.0f / Hdim);
            float inv = rsqrtf(qt * (1.0f / Hdim) - mu * mu + 1e-5f);
            int grow = rowbase + r;
#pragma unroll
            for (int nt = 0; nt < 4; nt++) {
                int col = w * 32 + nt * 8 + c2;
                float2 g = __ldg((const float2*)(gam + col));
                float2 b = __ldg((const float2*)(bet + col));
                float2 o;
                o.x = (vals[mt][h][2 * nt]     - mu) * inv * g.x + b.x;
                o.y = (vals[mt][h][2 * nt + 1] - mu) * inv * g.y + b.y;
                if (smA) {
                    *(half2*)(smA + ((size_t)(r * strideH + col)) * 2) = __floats2half2_rn(o.x, o.y);
                } else if (grow < nrows) {
                    size_t base = (size_t)grow * Hdim + col;
                    if (out1h) *(half2*)(out1h + base) = __floats2half2_rn(o.x, o.y);
                    if (out2) {
                        float2 rv = *(const float2*)(resid + base);
                        *(float2*)(out2 + base) = make_float2(o.x + rv.x, o.y + rv.y);
                    }
                }
            }
        }
}

// ---------------- fused CellBlock: both mp rounds ----------------
__global__ void __launch_bounds__(T, 4) k_cell(
    const __half* __restrict__ xh, const __half* __restrict__ aggh,
    const __half* __restrict__ w1, const __half* __restrict__ w2, const __half* __restrict__ w3,
    const float* __restrict__ b1, const float* __restrict__ b2, const float* __restrict__ b3,
    const float* __restrict__ gam, const float* __restrict__ bet,
    const float* __restrict__ x32, float* __restrict__ out_x, __half* __restrict__ xc2h,
    int nrows)
{
    extern __shared__ char smc[];
    uint32_t sa = smem_u32(smc);
    float* s_red = (float*)(smc + C_RED);
    int tid = threadIdx.x, w = tid >> 5, lane = tid & 31;
    int rowbase = blockIdx.x * 64;
    int arow = (lane & 7) + ((lane >> 3) & 1) * 8;
    int acol = (lane >> 4) * 8;
    int b_r = (lane & 7) + (lane >> 4) * 8;
    int b_c = ((lane >> 3) & 1) * 8;
    uint32_t aW  = sa + (uint32_t)(arow * SAc + acol) * 2;
    uint32_t sbW = sa + C_B + (uint32_t)w * (2 * SBW);
    uint32_t bo  = (uint32_t)(b_r * SB32 + b_c) * 2;
    float acc[4][4][4];
    int cc = 0;

    cpaH(xh, Hdim, 16, rowbase, nrows, sa, SAc, tid);
    cpaH(aggh, HALF, 8, rowbase, nrows, sa + 128u * 2, SAc, tid);
    cpaBs32(w1, 192, 0, sbW, w, lane);
    CPA_W1();                  // A staged; W1 chunk0 in flight
    __syncthreads();

#pragma unroll 1
    for (int rnd = 0; rnd < 2; rnd++) {
        // ---- L1: 6 chunks ----
        zero_acc(acc);
#pragma unroll
        for (int i = 0; i < 6; i++) {
            if (i < 5) cpaBs32(w1, 192, (i + 1) * 32, sbW + ((cc + 1) & 1) * SBW, w, lane);
            else       cpaBs32(w2, 128, 0,            sbW + ((cc + 1) & 1) * SBW, w, lane);
            CPA_W1(); __syncwarp();
            mma_chunk32(aW + (uint32_t)i * 64, sbW + (cc & 1) * SBW + bo, acc, SAc * 2); cc++;
        }
        __syncthreads();
        epi_act(acc, b1, smc, SAc, w, lane);
        __syncthreads();
        // ---- L2: 4 chunks ----
        zero_acc(acc);
#pragma unroll
        for (int i = 0; i < 4; i++) {
            if (i < 3) cpaBs32(w2, 128, (i + 1) * 32, sbW + ((cc + 1) & 1) * SBW, w, lane);
            else       cpaBs32(w3, 128, 0,            sbW + ((cc + 1) & 1) * SBW, w, lane);
            CPA_W1(); __syncwarp();
            mma_chunk32(aW + (uint32_t)i * 64, sbW + (cc & 1) * SBW + bo, acc, SAc * 2); cc++;
        }
        __syncthreads();
        epi_act(acc, b2, smc, SAc, w, lane);
        __syncthreads();
        // ---- L3: 4 chunks ----
        zero_acc(acc);
#pragma unroll
        for (int i = 0; i < 4; i++) {
            bool last = (rnd == 1) && (i == 3);
            if (!last) {
                if (i < 3) cpaBs32(w3, 128, (i + 1) * 32, sbW + ((cc + 1) & 1) * SBW, w, lane);
                else       cpaBs32(w1, 192, 0,            sbW + ((cc + 1) & 1) * SBW, w, lane);
                CPA_W1();
            } else { CPA_W0(); }
            __syncwarp();
            mma_chunk32(aW + (uint32_t)i * 64, sbW + (cc & 1) * SBW + bo, acc, SAc * 2); cc++;
        }
        __syncthreads();
        if (rnd == 0) {
            epi_ln(acc, b3, gam, bet, s_red, rowbase, nrows, smc, SAc,
                   nullptr, nullptr, nullptr, w, lane);
            __syncthreads();
        } else {
            epi_ln(acc, b3, gam, bet, s_red, rowbase, nrows, nullptr, SAc,
                   xc2h, x32, out_x, w, lane);
        }
    }
}

// ---------------- EdgeBlock: [ea | xc[s] | xc[r]](384) -> 128 -> 128 -> LN ----------------
__global__ void __launch_bounds__(T, 4) k_edge(
    const __half* __restrict__ eah, const float* __restrict__ ea32,
    const __half* __restrict__ xch, const int* __restrict__ ei,
    const __half* __restrict__ w1, const __half* __restrict__ w2, const __half* __restrict__ w3,
    const float* __restrict__ b1, const float* __restrict__ b2, const float* __restrict__ b3,
    const float* __restrict__ gam, const float* __restrict__ bet,
    float* __restrict__ out_e, int E)
{
    extern __shared__ char smc[];
    uint32_t sa = smem_u32(smc);
    float* s_red = (float*)(smc + E_RED);
    int tid = threadIdx.x, w = tid >> 5, lane = tid & 31;
    int rowbase = blockIdx.x * 64;
    int arow = (lane & 7) + ((lane >> 3) & 1) * 8;
    int acol = (lane >> 4) * 8;
    int b_r = (lane & 7) + (lane >> 4) * 8;
    int b_c = ((lane >> 3) & 1) * 8;
    uint32_t aW  = sa + (uint32_t)(arow * SAe + acol) * 2;
    uint32_t sbW = sa + E_B + (uint32_t)w * (2 * SBW);
    uint32_t bo  = (uint32_t)(b_r * SB32 + b_c) * 2;
    float acc[4][4][4];
    int cc = 0;

    // prologue: ea -> cols 0-127, W1 chunk0, gather1 -> cols 128-255
    cpaH(eah, Hdim, 16, rowbase, E, sa, SAe, tid);
    cpaBs32(w1, 384, 0, sbW, w, lane);
    cpaGh(xch, ei, rowbase, E, sa + 128u * 2, SAe, tid);
    CPA_W1();                 // ea + W1c0 done; gather1 in flight
    __syncthreads();

    // ---- L1: 12 chunks ----
    zero_acc(acc);
#pragma unroll 1
    for (int i = 0; i < 12; i++) {
        if (i == 4) { __syncthreads(); cpaGh(xch, ei + E, rowbase, E, sa, SAe, tid); }
        if (i == 8) __syncthreads();
        if (i < 11) cpaBs32(w1, 384, (i + 1) * 32, sbW + ((cc + 1) & 1) * SBW, w, lane);
        else        cpaBs32(w2, 128, 0,            sbW + ((cc + 1) & 1) * SBW, w, lane);
        if (i == 4) { CPA_W2(); } else { CPA_W1(); }
        __syncwarp();
        uint32_t aoff = (i < 8) ? (uint32_t)i * 64 : (uint32_t)(i - 8) * 64;
        mma_chunk32(aW + aoff, sbW + (cc & 1) * SBW + bo, acc, SAe * 2); cc++;
    }
    __syncthreads();
    epi_act(acc, b1, smc, SAe, w, lane);
    __syncthreads();
    // ---- L2: 4 chunks ----
    zero_acc(acc);
#pragma unroll
    for (int i = 0; i < 4; i++) {
        if (i < 3) cpaBs32(w2, 128, (i + 1) * 32, sbW + ((cc + 1) & 1) * SBW, w, lane);
        else       cpaBs32(w3, 128, 0,            sbW + ((cc + 1) & 1) * SBW, w, lane);
        CPA_W1(); __syncwarp();
        mma_chunk32(aW + (uint32_t)i * 64, sbW + (cc & 1) * SBW + bo, acc, SAe * 2); cc++;
    }
    __syncthreads();
    epi_act(acc, b2, smc, SAe, w, lane);
    __syncthreads();
    // ---- L3: 4 chunks ----
    zero_acc(acc);
#pragma unroll
    for (int i = 0; i < 4; i++) {
        if (i < 3) { cpaBs32(w3, 128, (i + 1) * 32, sbW + ((cc + 1) & 1) * SBW, w, lane); CPA_W1(); }
        else       { CPA_W0(); }
        __syncwarp();
        mma_chunk32(aW + (uint32_t)i * 64, sbW + (cc & 1) * SBW + bo, acc, SAe * 2); cc++;
    }
    __syncthreads();
    epi_ln(acc, b3, gam, bet, s_red, rowbase, E, nullptr, SAe, nullptr, ea32, out_e, w, lane);
}

// ---------------- host ----------------
extern "C" void kernel_launch(void* const* d_in, const int* in_sizes, int n_in,
                              void* d_out, int out_size)
{
    const float* x     = (const float*)d_in[0];
    const float* ea    = (const float*)d_in[1];
    const float* cb_w1 = (const float*)d_in[2];
    const float* cb_b1 = (const float*)d_in[3];
    const float* cb_w2 = (const float*)d_in[4];
    const float* cb_b2 = (const float*)d_in[5];
    const float* cb_w3 = (const float*)d_in[6];
    const float* cb_b3 = (const float*)d_in[7];
    const float* cb_g  = (const float*)d_in[8];
    const float* cb_be = (const float*)d_in[9];
    const float* eb_w1 = (const float*)d_in[10];
    const float* eb_b1 = (const float*)d_in[11];
    const float* eb_w2 = (const float*)d_in[12];
    const float* eb_b2 = (const float*)d_in[13];
    const float* eb_w3 = (const float*)d_in[14];
    const float* eb_b3 = (const float*)d_in[15];
    const float* eb_g  = (const float*)d_in[16];
    const float* eb_be = (const float*)d_in[17];
    const int*   ei    = (const int*)d_in[18];

    int N = in_sizes[0] / Hdim;
    int E = in_sizes[1] / Hdim;
    float* out_x = (float*)d_out;
    float* out_e = out_x + (size_t)N * Hdim;

    __half *xh, *aggh, *xc2h, *eah, *wt;
    float* agg;
    cudaGetSymbolAddress((void**)&xh, g_xh);
    cudaGetSymbolAddress((void**)&aggh, g_aggh);
    cudaGetSymbolAddress((void**)&xc2h, g_xc2h);
    cudaGetSymbolAddress((void**)&eah, g_eah);
    cudaGetSymbolAddress((void**)&wt, g_wt);
    cudaGetSymbolAddress((void**)&agg, g_agg);

    cudaFuncSetAttribute(k_cell, cudaFuncAttributeMaxDynamicSharedMemorySize, SMEM_CELL);
    cudaFuncSetAttribute(k_edge, cudaFuncAttributeMaxDynamicSharedMemorySize, SMEM_EDGE);

    const int OCB1 = 0, OCB2 = 24576, OCB3 = 40960, OEB1 = 57344, OEB2 = 106496, OEB3 = 122880;

    k_prep_all<<<(139264 + 255) / 256, 256>>>(cb_w1, cb_w2, cb_w3, eb_w1, eb_w2, eb_w3);
    k_init<<<(N * 32 + 255) / 256, 256>>>(x, N);
    k_scatter<<<(E * 32 + 255) / 256, 256>>>(ea, ei, E);
    k_cvt<<<(N * 16 + 255) / 256, 256>>>(agg, aggh, N * 16);

    int cgrid = (N + 63) / 64;
    int egrid = (E + 63) / 64;

    k_cell<<<cgrid, T, SMEM_CELL>>>(xh, aggh, wt + OCB1, wt + OCB2, wt + OCB3,
        cb_b1, cb_b2, cb_b3, cb_g, cb_be, x, out_x, xc2h, N);

    k_edge<<<egrid, T, SMEM_EDGE>>>(eah, ea, xc2h, ei, wt + OEB1, wt + OEB2, wt + OEB3,
        eb_b1, eb_b2, eb_b3, eb_g, eb_be, out_e, E);
}